// round 1
// baseline (speedup 1.0000x reference)
#include <cuda_runtime.h>
#include <math.h>

#define B_  16
#define N_  577
#define C_  1024
#define H_  16
#define D_  64
#define NP_ 640                 // padded sequence length per (b,h) slab
#define M_  (B_*N_)             // 9232 rows
#define OUT_ELEMS (M_*C_)       // 9453568
#define OFF_ATTN  OUT_ELEMS
#define OFF_LOG   (OUT_ELEMS + B_*N_)

// ---------------- scratch (device globals; zero-initialized at load) --------
__device__ float g_qkv[3][B_*H_*NP_*D_];   // q (pre-scaled), k, v : [B,H,NP,D]
__device__ float g_attn[M_*C_];            // pre-proj attention output [B,N,C]
__device__ float g_cl[B_*H_*N_];           // CLS row-0 logits per head
__device__ float g_clm[B_*H_];             // row-0 max per head
__device__ float g_cls[B_*H_];             // row-0 sum(exp) per head

// ============================================================================
// GEMM:  Y[m,j] = dot(A[m,:1024], W[j,:1024]) + bias[j]
//   mode 0: A = x, W = w_qkv (j < 3072)  -> scatter to g_qkv (q scaled)
//   mode 1: A = g_attn, W = w_proj       -> out[m*1024 + j]
// 128x128 tile, BK=8, 256 threads, 8x8 per thread.
// ============================================================================
__global__ __launch_bounds__(256) void gemm_k(const float* __restrict__ Aarg,
                                              const float* __restrict__ W,
                                              const float* __restrict__ bias,
                                              float* __restrict__ out,
                                              int mode)
{
    const float* __restrict__ A = (mode == 0) ? Aarg : g_attn;
    __shared__ float As[8][128];
    __shared__ float Bs[8][128];

    const int t  = threadIdx.x;
    const int tx = t & 15, ty = t >> 4;
    const int m0 = blockIdx.y * 128;
    const int j0 = blockIdx.x * 128;

    const int lr = t >> 1;          // 0..127 : tile row being loaded
    const int lf = (t & 1) * 4;     // 0 or 4 : k sub-offset

    float acc[8][8];
#pragma unroll
    for (int i = 0; i < 8; i++)
#pragma unroll
        for (int j = 0; j < 8; j++) acc[i][j] = 0.f;

    const int  am   = m0 + lr;
    const bool aval = (am < M_);
    const float* aptr = A + (size_t)(aval ? am : 0) * 1024 + lf;
    const float* bptr = W + (size_t)(j0 + lr) * 1024 + lf;

    for (int k0 = 0; k0 < 1024; k0 += 8) {
        float4 av = aval ? *(const float4*)(aptr + k0) : make_float4(0.f,0.f,0.f,0.f);
        float4 bv = *(const float4*)(bptr + k0);
        As[lf+0][lr] = av.x; As[lf+1][lr] = av.y; As[lf+2][lr] = av.z; As[lf+3][lr] = av.w;
        Bs[lf+0][lr] = bv.x; Bs[lf+1][lr] = bv.y; Bs[lf+2][lr] = bv.z; Bs[lf+3][lr] = bv.w;
        __syncthreads();
#pragma unroll
        for (int k = 0; k < 8; k++) {
            float a[8], b[8];
            *(float4*)(a)     = *(const float4*)&As[k][ty*8];
            *(float4*)(a + 4) = *(const float4*)&As[k][ty*8 + 4];
            *(float4*)(b)     = *(const float4*)&Bs[k][tx*8];
            *(float4*)(b + 4) = *(const float4*)&Bs[k][tx*8 + 4];
#pragma unroll
            for (int i = 0; i < 8; i++)
#pragma unroll
                for (int j = 0; j < 8; j++)
                    acc[i][j] = fmaf(a[i], b[j], acc[i][j]);
        }
        __syncthreads();
    }

    if (mode == 0) {
        // scatter into g_qkv[three][((b*H+h)*NP + n)*D + d], scale q by 1/8
#pragma unroll
        for (int i = 0; i < 8; i++) {
            int m = m0 + ty*8 + i;
            if (m >= M_) continue;
            int bb = m / N_;
            int n  = m - bb * N_;
#pragma unroll
            for (int j = 0; j < 8; j++) {
                int jj = j0 + tx*8 + j;
                float v = acc[i][j] + bias[jj];
                int three = jj >> 10;
                int h     = (jj >> 6) & 15;
                int d     = jj & 63;
                if (three == 0) v *= 0.125f;
                g_qkv[three][(((size_t)(bb*H_ + h))*NP_ + n)*D_ + d] = v;
            }
        }
    } else {
#pragma unroll
        for (int i = 0; i < 8; i++) {
            int m = m0 + ty*8 + i;
            if (m >= M_) continue;
            float* op = out + (size_t)m*1024 + j0 + tx*8;
#pragma unroll
            for (int j = 0; j < 8; j++)
                op[j] = acc[i][j] + bias[j0 + tx*8 + j];
        }
    }
}

// ============================================================================
// Fused attention: per (b, h, 64-query tile), flash-style online softmax.
// 256 threads = 16x16, each owns a 4x4 patch of the 64x64 S tile and 4x4 of O.
// dynamic smem: Qs[d][i] 16K | Ks[d][j] 16K | Vs[j][d] 16K | Ps[i][j] 16K
// ============================================================================
__global__ __launch_bounds__(256) void attn_k()
{
    extern __shared__ float smem[];
    float (*Qs)[64] = (float (*)[64])(smem);            // [d][i]
    float (*Ks)[64] = (float (*)[64])(smem + 4096);     // [d][j]
    float (*Vs)[64] = (float (*)[64])(smem + 8192);     // [j][d]
    float (*Ps)[64] = (float (*)[64])(smem + 12288);    // [i][j]

    const int qt = blockIdx.x, h = blockIdx.y, b = blockIdx.z;
    const size_t slab = ((size_t)(b*H_ + h)) * NP_ * D_;
    const float* __restrict__ q = g_qkv[0] + slab;
    const float* __restrict__ k = g_qkv[1] + slab;
    const float* __restrict__ v = g_qkv[2] + slab;

    const int t  = threadIdx.x;
    const int tx = t & 15, ty = t >> 4;
    const int lr  = t >> 2;       // 0..63 : row being loaded
    const int lc4 = t & 3;        // float4 sub-index

    // load Q tile (transposed into Qs[d][i])
#pragma unroll
    for (int c = 0; c < 4; c++) {
        int d0 = (lc4 + c*4) * 4;
        float4 qv = *(const float4*)(q + (size_t)(qt*64 + lr)*D_ + d0);
        Qs[d0+0][lr] = qv.x; Qs[d0+1][lr] = qv.y; Qs[d0+2][lr] = qv.z; Qs[d0+3][lr] = qv.w;
    }

    float m_i[4], l_i[4], o[4][4];
#pragma unroll
    for (int i = 0; i < 4; i++) {
        m_i[i] = -1e30f; l_i[i] = 0.f;
#pragma unroll
        for (int j = 0; j < 4; j++) o[i][j] = 0.f;
    }

    for (int kt = 0; kt < 10; kt++) {
        __syncthreads();   // protect Ks/Vs/Ps reuse (also orders Qs on first iter)
        // load K (transposed) and V (natural) tiles
#pragma unroll
        for (int c = 0; c < 4; c++) {
            int d0 = (lc4 + c*4) * 4;
            float4 kv = *(const float4*)(k + (size_t)(kt*64 + lr)*D_ + d0);
            Ks[d0+0][lr] = kv.x; Ks[d0+1][lr] = kv.y; Ks[d0+2][lr] = kv.z; Ks[d0+3][lr] = kv.w;
            float4 vv = *(const float4*)(v + (size_t)(kt*64 + lr)*D_ + d0);
            *(float4*)&Vs[lr][d0] = vv;
        }
        __syncthreads();

        // S = Q K^T  (64x64 distributed 4x4 per thread)
        float s[4][4];
#pragma unroll
        for (int i = 0; i < 4; i++)
#pragma unroll
            for (int j = 0; j < 4; j++) s[i][j] = 0.f;
#pragma unroll
        for (int d = 0; d < 64; d++) {
            float a[4], bb[4];
            *(float4*)a  = *(const float4*)&Qs[d][ty*4];
            *(float4*)bb = *(const float4*)&Ks[d][tx*4];
#pragma unroll
            for (int i = 0; i < 4; i++)
#pragma unroll
                for (int j = 0; j < 4; j++)
                    s[i][j] = fmaf(a[i], bb[j], s[i][j]);
        }

        // mask invalid keys
        const int jg = kt*64 + tx*4;
#pragma unroll
        for (int j = 0; j < 4; j++)
            if (jg + j >= N_) {
#pragma unroll
                for (int i = 0; i < 4; i++) s[i][j] = -1e30f;
            }

        // online softmax update (row reductions across the 16 tx lanes)
#pragma unroll
        for (int i = 0; i < 4; i++) {
            float rmax = fmaxf(fmaxf(s[i][0], s[i][1]), fmaxf(s[i][2], s[i][3]));
#pragma unroll
            for (int off = 8; off > 0; off >>= 1)
                rmax = fmaxf(rmax, __shfl_xor_sync(0xffffffffu, rmax, off, 16));
            float mn    = fmaxf(m_i[i], rmax);
            float alpha = __expf(m_i[i] - mn);
            m_i[i] = mn;
            float rsum = 0.f;
#pragma unroll
            for (int j = 0; j < 4; j++) {
                float p = __expf(s[i][j] - mn);
                s[i][j] = p;
                rsum += p;
            }
#pragma unroll
            for (int off = 8; off > 0; off >>= 1)
                rsum += __shfl_xor_sync(0xffffffffu, rsum, off, 16);
            l_i[i] = l_i[i] * alpha + rsum;
#pragma unroll
            for (int j = 0; j < 4; j++) o[i][j] *= alpha;
        }

        // stash P (natural layout, conflict-free float4 stores)
#pragma unroll
        for (int i = 0; i < 4; i++)
            *(float4*)&Ps[ty*4 + i][tx*4] = *(float4*)&s[i][0];
        __syncthreads();

        // O += P V   (contraction over j; a-loads broadcast/2-way, b float4)
#pragma unroll 4
        for (int j = 0; j < 64; j++) {
            float a0 = Ps[ty*4+0][j], a1 = Ps[ty*4+1][j],
                  a2 = Ps[ty*4+2][j], a3 = Ps[ty*4+3][j];
            float bb[4];
            *(float4*)bb = *(const float4*)&Vs[j][tx*4];
#pragma unroll
            for (int jj = 0; jj < 4; jj++) {
                o[0][jj] = fmaf(a0, bb[jj], o[0][jj]);
                o[1][jj] = fmaf(a1, bb[jj], o[1][jj]);
                o[2][jj] = fmaf(a2, bb[jj], o[2][jj]);
                o[3][jj] = fmaf(a3, bb[jj], o[3][jj]);
            }
        }
    }

    // write O / l  ->  g_attn[b, n, h*64 + d]
#pragma unroll
    for (int i = 0; i < 4; i++) {
        int n = qt*64 + ty*4 + i;
        if (n >= N_) continue;
        float inv = 1.f / l_i[i];
        float4 w;
        w.x = o[i][0]*inv; w.y = o[i][1]*inv; w.z = o[i][2]*inv; w.w = o[i][3]*inv;
        *(float4*)&g_attn[((size_t)(b*N_ + n))*C_ + h*64 + tx*4] = w;
    }
}

// ============================================================================
// CLS row-0 logits per (b,h) + online (max, sumexp)
// ============================================================================
__global__ __launch_bounds__(128) void cls_logits_k()
{
    const int h = blockIdx.x, b = blockIdx.y;
    const size_t slab = ((size_t)(b*H_ + h)) * NP_ * D_;
    const float* __restrict__ q = g_qkv[0] + slab;   // row 0 (already scaled)
    const float* __restrict__ k = g_qkv[1] + slab;

    __shared__ float qs[64];
    const int t = threadIdx.x;
    if (t < 64) qs[t] = q[t];
    __syncthreads();

    float m_ = -1e30f, s_ = 0.f;
    for (int n = t; n < N_; n += 128) {
        float acc = 0.f;
#pragma unroll
        for (int d = 0; d < 64; d++) acc = fmaf(qs[d], k[(size_t)n*D_ + d], acc);
        g_cl[(size_t)(b*H_ + h)*N_ + n] = acc;
        if (acc > m_) { s_ = s_ * __expf(m_ - acc) + 1.f; m_ = acc; }
        else          { s_ += __expf(acc - m_); }
    }

    __shared__ float sm[128], ss[128];
    sm[t] = m_; ss[t] = s_;
    __syncthreads();
    for (int o = 64; o > 0; o >>= 1) {
        if (t < o) {
            float m2 = sm[t+o], s2 = ss[t+o];
            float mm = fmaxf(sm[t], m2);
            ss[t] = ss[t] * __expf(sm[t] - mm) + s2 * __expf(m2 - mm);
            sm[t] = mm;
        }
        __syncthreads();
    }
    if (t == 0) { g_clm[b*H_ + h] = sm[0]; g_cls[b*H_ + h] = ss[0]; }
}

// ============================================================================
// Average over heads -> class_token_attention, class_token_logits
// ============================================================================
__global__ __launch_bounds__(256) void cls_out_k(float* __restrict__ out_attn,
                                                 float* __restrict__ out_log)
{
    const int b = blockIdx.x;
    for (int n = threadIdx.x; n < N_; n += 256) {
        float sa = 0.f, sl = 0.f;
#pragma unroll
        for (int h = 0; h < H_; h++) {
            float lg = g_cl[(size_t)(b*H_ + h)*N_ + n];
            sl += lg;
            sa += __expf(lg - g_clm[b*H_ + h]) / g_cls[b*H_ + h];
        }
        out_attn[b*N_ + n] = sa * (1.0f / H_);
        out_log [b*N_ + n] = sl * (1.0f / H_);
    }
}

// ============================================================================
extern "C" void kernel_launch(void* const* d_in, const int* in_sizes, int n_in,
                              void* d_out, int out_size)
{
    const float* x      = (const float*)d_in[0];
    const float* w_qkv  = (const float*)d_in[1];
    const float* b_qkv  = (const float*)d_in[2];
    const float* w_proj = (const float*)d_in[3];
    const float* b_proj = (const float*)d_in[4];
    float* out = (float*)d_out;

    static bool attr_set = false;
    if (!attr_set) {
        cudaFuncSetAttribute(attn_k, cudaFuncAttributeMaxDynamicSharedMemorySize, 65536);
        attr_set = true;
    }

    // 1) QKV projection -> scatter to g_qkv
    gemm_k<<<dim3(3072/128, (M_ + 127)/128), 256>>>(x, w_qkv, b_qkv, nullptr, 0);
    // 2) CLS row-0 logits per head
    cls_logits_k<<<dim3(H_, B_), 128>>>();
    // 3) fused attention -> g_attn
    attn_k<<<dim3(10, H_, B_), 256, 65536>>>();
    // 4) CLS averages
    cls_out_k<<<B_, 256>>>(out + OFF_ATTN, out + OFF_LOG);
    // 5) output projection -> d_out
    gemm_k<<<dim3(1024/128, (M_ + 127)/128), 256>>>(nullptr, w_proj, b_proj, out, 1);
}

// round 3
// speedup vs baseline: 2.3024x; 2.3024x over previous
#include <cuda_runtime.h>
#include <math.h>

#define B_  16
#define N_  577
#define C_  1024
#define H_  16
#define D_  64
#define NP_ 640                 // padded sequence length per (b,h) slab
#define M_  (B_*N_)             // 9232 rows
#define OUT_ELEMS (M_*C_)       // 9453568
#define OFF_ATTN  OUT_ELEMS
#define OFF_LOG   (OUT_ELEMS + B_*N_)

// ---------------- scratch (device globals) ----------------------------------
__device__ float g_qkv[3][B_*H_*NP_*D_];   // q (pre-scaled), k, v : [B,H,NP,D]
__device__ float g_attn[M_*C_];            // pre-proj attention output [B,N,C]
__device__ float g_cl[B_*H_*N_];           // CLS row-0 logits per head
__device__ float g_clm[B_*H_];             // row-0 max per head
__device__ float g_cls[B_*H_];             // row-0 sum(exp) per head

__device__ __forceinline__ unsigned int f2tf32(float f) {
    unsigned int u;
    asm("cvt.rna.tf32.f32 %0, %1;" : "=r"(u) : "f"(f));
    return u;
}

#define MMA_TF32(d, a0,a1,a2,a3, b0,b1)                                        \
    asm volatile(                                                              \
        "mma.sync.aligned.m16n8k8.row.col.f32.tf32.tf32.f32 "                  \
        "{%0,%1,%2,%3}, {%4,%5,%6,%7}, {%8,%9}, {%0,%1,%2,%3};"                \
        : "+f"(d[0]), "+f"(d[1]), "+f"(d[2]), "+f"(d[3])                       \
        : "r"(a0), "r"(a1), "r"(a2), "r"(a3), "r"(b0), "r"(b1))

// ============================================================================
// tf32 tensor-core GEMM:  Y[m,j] = dot(A[m,:1024], W[j,:1024]) + bias[j]
//   mode 0: A = x, W = w_qkv (j < 3072)  -> scatter to g_qkv (q scaled)
//   mode 1: A = g_attn, W = w_proj       -> out[m*1024 + j]
// 128x128 block tile, BK=32, 256 thr = 8 warps (2m x 4n), warp tile 64x32.
// ============================================================================
__global__ __launch_bounds__(256) void gemm_tc(const float* __restrict__ Aarg,
                                               const float* __restrict__ W,
                                               const float* __restrict__ bias,
                                               float* __restrict__ out,
                                               int mode)
{
    const float* __restrict__ A = (mode == 0) ? Aarg : g_attn;
    __shared__ unsigned int As[128][36];   // [m][k], stride 36 words (36%32=4)
    __shared__ unsigned int Bs[128][36];   // [n][k]

    const int t  = threadIdx.x;
    const int m0 = blockIdx.y * 128;
    const int j0 = blockIdx.x * 128;

    const int lrow = t >> 1;
    const int lk   = (t & 1) * 16;
    const int  am   = m0 + lrow;
    const bool aval = (am < M_);
    const float* aptr = A + (size_t)(aval ? am : 0) * 1024 + lk;
    const float* bptr = W + (size_t)(j0 + lrow) * 1024 + lk;

    const int w    = t >> 5;
    const int lane = t & 31;
    const int wm   = (w & 1) * 64;
    const int wn   = (w >> 1) * 32;
    const int g    = lane >> 2;
    const int t4   = lane & 3;

    float acc[4][4][4];
#pragma unroll
    for (int mt = 0; mt < 4; mt++)
#pragma unroll
        for (int nt = 0; nt < 4; nt++)
#pragma unroll
            for (int r = 0; r < 4; r++) acc[mt][nt][r] = 0.f;

    for (int k0 = 0; k0 < 1024; k0 += 32) {
        float4 av[4], bv[4];
#pragma unroll
        for (int c = 0; c < 4; c++) {
            av[c] = aval ? *(const float4*)(aptr + k0 + c*4)
                         : make_float4(0.f, 0.f, 0.f, 0.f);
            bv[c] = *(const float4*)(bptr + k0 + c*4);
        }
        __syncthreads();
#pragma unroll
        for (int c = 0; c < 4; c++) {
            As[lrow][lk + c*4 + 0] = f2tf32(av[c].x);
            As[lrow][lk + c*4 + 1] = f2tf32(av[c].y);
            As[lrow][lk + c*4 + 2] = f2tf32(av[c].z);
            As[lrow][lk + c*4 + 3] = f2tf32(av[c].w);
            Bs[lrow][lk + c*4 + 0] = f2tf32(bv[c].x);
            Bs[lrow][lk + c*4 + 1] = f2tf32(bv[c].y);
            Bs[lrow][lk + c*4 + 2] = f2tf32(bv[c].z);
            Bs[lrow][lk + c*4 + 3] = f2tf32(bv[c].w);
        }
        __syncthreads();

#pragma unroll
        for (int kb = 0; kb < 32; kb += 8) {
            unsigned int aR[4][4], bR[4][2];
#pragma unroll
            for (int mt = 0; mt < 4; mt++) {
                int r = wm + mt*16 + g;
                aR[mt][0] = As[r    ][kb + t4    ];
                aR[mt][1] = As[r + 8][kb + t4    ];
                aR[mt][2] = As[r    ][kb + t4 + 4];
                aR[mt][3] = As[r + 8][kb + t4 + 4];
            }
#pragma unroll
            for (int nt = 0; nt < 4; nt++) {
                int c = wn + nt*8 + g;
                bR[nt][0] = Bs[c][kb + t4    ];
                bR[nt][1] = Bs[c][kb + t4 + 4];
            }
#pragma unroll
            for (int mt = 0; mt < 4; mt++)
#pragma unroll
                for (int nt = 0; nt < 4; nt++)
                    MMA_TF32(acc[mt][nt],
                             aR[mt][0], aR[mt][1], aR[mt][2], aR[mt][3],
                             bR[nt][0], bR[nt][1]);
        }
    }

    if (mode == 0) {
#pragma unroll
        for (int mt = 0; mt < 4; mt++) {
#pragma unroll
            for (int half = 0; half < 2; half++) {
                int m = m0 + wm + mt*16 + g + half*8;
                if (m >= M_) continue;
                int bb = m / N_;
                int n  = m - bb * N_;
#pragma unroll
                for (int nt = 0; nt < 4; nt++) {
#pragma unroll
                    for (int e = 0; e < 2; e++) {
                        int jj = j0 + wn + nt*8 + t4*2 + e;
                        float v = acc[mt][nt][half*2 + e] + bias[jj];
                        int three = jj >> 10;
                        int h     = (jj >> 6) & 15;
                        int d     = jj & 63;
                        if (three == 0) v *= 0.125f;
                        g_qkv[three][(((size_t)(bb*H_ + h))*NP_ + n)*D_ + d] = v;
                    }
                }
            }
        }
    } else {
#pragma unroll
        for (int mt = 0; mt < 4; mt++) {
#pragma unroll
            for (int half = 0; half < 2; half++) {
                int m = m0 + wm + mt*16 + g + half*8;
                if (m >= M_) continue;
#pragma unroll
                for (int nt = 0; nt < 4; nt++) {
                    int jj = j0 + wn + nt*8 + t4*2;
                    float2 v;
                    v.x = acc[mt][nt][half*2 + 0] + bias[jj];
                    v.y = acc[mt][nt][half*2 + 1] + bias[jj + 1];
                    *(float2*)&out[(size_t)m*1024 + jj] = v;
                }
            }
        }
    }
}

// ============================================================================
// Fused attention on tensor cores (tf32 mma), flash-style online softmax.
// 128 thr = 4 warps; warp owns 16 query rows of the 64-row Q tile.
// smem (dynamic, stride 68 words): Qs[i][d] | Ks[j][d] | Vt[d][j] | Ps[i][j]
// ============================================================================
#define AST 68
__global__ __launch_bounds__(128) void attn_tc()
{
    extern __shared__ unsigned int smu[];
    unsigned int (*Qs)[AST] = (unsigned int (*)[AST])smu;          // [i][d]
    unsigned int (*Ks)[AST] = Qs + 64;                             // [j][d]
    unsigned int (*Vt)[AST] = Qs + 128;                            // [d][j]
    unsigned int (*Ps)[AST] = Qs + 192;                            // [i][j]

    const int qt = blockIdx.x, h = blockIdx.y, b = blockIdx.z;
    const size_t slab = ((size_t)(b*H_ + h)) * NP_ * D_;
    const float* __restrict__ q = g_qkv[0] + slab;
    const float* __restrict__ k = g_qkv[1] + slab;
    const float* __restrict__ v = g_qkv[2] + slab;

    const int t    = threadIdx.x;
    const int w    = t >> 5;
    const int lane = t & 31;
    const int g    = lane >> 2;
    const int t4   = lane & 3;
    const int qb   = w * 16;              // warp's query-row base within tile

    // loaders: row = t>>1 (0..63), k half = (t&1)*32
    const int lrow = t >> 1;
    const int lk   = (t & 1) * 32;

    // ---- load Q tile (rows up to 640 exist in padded g_qkv) ----
    {
        const float* qp = q + (size_t)(qt*64 + lrow)*D_ + lk;
#pragma unroll
        for (int c = 0; c < 8; c++) {
            float4 val = *(const float4*)(qp + c*4);
            Qs[lrow][lk + c*4 + 0] = f2tf32(val.x);
            Qs[lrow][lk + c*4 + 1] = f2tf32(val.y);
            Qs[lrow][lk + c*4 + 2] = f2tf32(val.z);
            Qs[lrow][lk + c*4 + 3] = f2tf32(val.w);
        }
    }

    float m_i[2], l_i[2];
    m_i[0] = m_i[1] = -1e30f;
    l_i[0] = l_i[1] = 0.f;
    float o[8][4];
#pragma unroll
    for (int nt = 0; nt < 8; nt++)
#pragma unroll
        for (int r = 0; r < 4; r++) o[nt][r] = 0.f;

    for (int kt = 0; kt < 10; kt++) {
        __syncthreads();   // prior-iteration readers of Ks/Vt/Ps done; Qs visible
        // ---- load K -> Ks[j][d], V -> Vt[d][j] (transposed) ----
        {
            const float* kp = k + (size_t)(kt*64 + lrow)*D_ + lk;
            const float* vp = v + (size_t)(kt*64 + lrow)*D_ + lk;
#pragma unroll
            for (int c = 0; c < 8; c++) {
                float4 kv = *(const float4*)(kp + c*4);
                Ks[lrow][lk + c*4 + 0] = f2tf32(kv.x);
                Ks[lrow][lk + c*4 + 1] = f2tf32(kv.y);
                Ks[lrow][lk + c*4 + 2] = f2tf32(kv.z);
                Ks[lrow][lk + c*4 + 3] = f2tf32(kv.w);
                float4 vv = *(const float4*)(vp + c*4);
                Vt[lk + c*4 + 0][lrow] = f2tf32(vv.x);
                Vt[lk + c*4 + 1][lrow] = f2tf32(vv.y);
                Vt[lk + c*4 + 2][lrow] = f2tf32(vv.z);
                Vt[lk + c*4 + 3][lrow] = f2tf32(vv.w);
            }
        }
        __syncthreads();

        // ---- S = Q K^T : warp computes 16x64, thread holds s[8][4] ----
        float s[8][4];
#pragma unroll
        for (int nt = 0; nt < 8; nt++)
#pragma unroll
            for (int r = 0; r < 4; r++) s[nt][r] = 0.f;
#pragma unroll
        for (int k0 = 0; k0 < 64; k0 += 8) {
            unsigned int a0 = Qs[qb + g    ][k0 + t4    ];
            unsigned int a1 = Qs[qb + g + 8][k0 + t4    ];
            unsigned int a2 = Qs[qb + g    ][k0 + t4 + 4];
            unsigned int a3 = Qs[qb + g + 8][k0 + t4 + 4];
#pragma unroll
            for (int nt = 0; nt < 8; nt++) {
                unsigned int b0 = Ks[nt*8 + g][k0 + t4    ];
                unsigned int b1 = Ks[nt*8 + g][k0 + t4 + 4];
                MMA_TF32(s[nt], a0, a1, a2, a3, b0, b1);
            }
        }

        // ---- mask padded keys ----
        const int jg0 = kt*64 + 2*t4;
#pragma unroll
        for (int nt = 0; nt < 8; nt++) {
            int c0 = jg0 + nt*8;
            if (c0     >= N_) { s[nt][0] = -1e30f; s[nt][2] = -1e30f; }
            if (c0 + 1 >= N_) { s[nt][1] = -1e30f; s[nt][3] = -1e30f; }
        }

        // ---- online softmax (rows g and g+8; row spread over 4 t4-lanes) ----
        float rm0 = -1e30f, rm1 = -1e30f;
#pragma unroll
        for (int nt = 0; nt < 8; nt++) {
            rm0 = fmaxf(rm0, fmaxf(s[nt][0], s[nt][1]));
            rm1 = fmaxf(rm1, fmaxf(s[nt][2], s[nt][3]));
        }
        rm0 = fmaxf(rm0, __shfl_xor_sync(0xffffffffu, rm0, 1));
        rm0 = fmaxf(rm0, __shfl_xor_sync(0xffffffffu, rm0, 2));
        rm1 = fmaxf(rm1, __shfl_xor_sync(0xffffffffu, rm1, 1));
        rm1 = fmaxf(rm1, __shfl_xor_sync(0xffffffffu, rm1, 2));

        float mn0 = fmaxf(m_i[0], rm0), mn1 = fmaxf(m_i[1], rm1);
        float al0 = __expf(m_i[0] - mn0), al1 = __expf(m_i[1] - mn1);
        m_i[0] = mn0; m_i[1] = mn1;

        float rs0 = 0.f, rs1 = 0.f;
#pragma unroll
        for (int nt = 0; nt < 8; nt++) {
            float p0 = __expf(s[nt][0] - mn0);
            float p1 = __expf(s[nt][1] - mn0);
            float p2 = __expf(s[nt][2] - mn1);
            float p3 = __expf(s[nt][3] - mn1);
            rs0 += p0 + p1;
            rs1 += p2 + p3;
            uint2 u0; u0.x = f2tf32(p0); u0.y = f2tf32(p1);
            *(uint2*)&Ps[qb + g    ][nt*8 + 2*t4] = u0;
            uint2 u1; u1.x = f2tf32(p2); u1.y = f2tf32(p3);
            *(uint2*)&Ps[qb + g + 8][nt*8 + 2*t4] = u1;
            o[nt][0] *= al0; o[nt][1] *= al0;
            o[nt][2] *= al1; o[nt][3] *= al1;
        }
        rs0 += __shfl_xor_sync(0xffffffffu, rs0, 1);
        rs0 += __shfl_xor_sync(0xffffffffu, rs0, 2);
        rs1 += __shfl_xor_sync(0xffffffffu, rs1, 1);
        rs1 += __shfl_xor_sync(0xffffffffu, rs1, 2);
        l_i[0] = l_i[0]*al0 + rs0;
        l_i[1] = l_i[1]*al1 + rs1;

        __syncwarp();   // P visible within warp (PV reads only own warp's rows)

        // ---- O += P V : A = Ps rows [qb..qb+16), B = Vt (n = d-dim) ----
#pragma unroll
        for (int k0 = 0; k0 < 64; k0 += 8) {
            unsigned int a0 = Ps[qb + g    ][k0 + t4    ];
            unsigned int a1 = Ps[qb + g + 8][k0 + t4    ];
            unsigned int a2 = Ps[qb + g    ][k0 + t4 + 4];
            unsigned int a3 = Ps[qb + g + 8][k0 + t4 + 4];
#pragma unroll
            for (int nt = 0; nt < 8; nt++) {
                unsigned int b0 = Vt[nt*8 + g][k0 + t4    ];
                unsigned int b1 = Vt[nt*8 + g][k0 + t4 + 4];
                MMA_TF32(o[nt], a0, a1, a2, a3, b0, b1);
            }
        }
    }

    // ---- write O/l -> g_attn[b, n, h*64 + d] ----
    const int n0 = qt*64 + qb + g;
    const float inv0 = 1.f / l_i[0];
    const float inv1 = 1.f / l_i[1];
#pragma unroll
    for (int nt = 0; nt < 8; nt++) {
        int dcol = h*64 + nt*8 + 2*t4;
        if (n0 < N_) {
            float2 v0; v0.x = o[nt][0]*inv0; v0.y = o[nt][1]*inv0;
            *(float2*)&g_attn[((size_t)(b*N_ + n0))*C_ + dcol] = v0;
        }
        if (n0 + 8 < N_) {
            float2 v1; v1.x = o[nt][2]*inv1; v1.y = o[nt][3]*inv1;
            *(float2*)&g_attn[((size_t)(b*N_ + n0 + 8))*C_ + dcol] = v1;
        }
    }
}

// ============================================================================
// CLS row-0 logits per (b,h) + online (max, sumexp)
// ============================================================================
__global__ __launch_bounds__(128) void cls_logits_k()
{
    const int h = blockIdx.x, b = blockIdx.y;
    const size_t slab = ((size_t)(b*H_ + h)) * NP_ * D_;
    const float* __restrict__ q = g_qkv[0] + slab;
    const float* __restrict__ k = g_qkv[1] + slab;

    __shared__ float qs[64];
    const int t = threadIdx.x;
    if (t < 64) qs[t] = q[t];
    __syncthreads();

    float m_ = -1e30f, s_ = 0.f;
    for (int n = t; n < N_; n += 128) {
        float acc = 0.f;
#pragma unroll
        for (int d = 0; d < 64; d++) acc = fmaf(qs[d], k[(size_t)n*D_ + d], acc);
        g_cl[(size_t)(b*H_ + h)*N_ + n] = acc;
        if (acc > m_) { s_ = s_ * __expf(m_ - acc) + 1.f; m_ = acc; }
        else          { s_ += __expf(acc - m_); }
    }

    __shared__ float sm[128], ss[128];
    sm[t] = m_; ss[t] = s_;
    __syncthreads();
    for (int o = 64; o > 0; o >>= 1) {
        if (t < o) {
            float m2 = sm[t+o], s2 = ss[t+o];
            float mm = fmaxf(sm[t], m2);
            ss[t] = ss[t] * __expf(sm[t] - mm) + s2 * __expf(m2 - mm);
            sm[t] = mm;
        }
        __syncthreads();
    }
    if (t == 0) { g_clm[b*H_ + h] = sm[0]; g_cls[b*H_ + h] = ss[0]; }
}

// ============================================================================
// Average over heads -> class_token_attention, class_token_logits
// ============================================================================
__global__ __launch_bounds__(256) void cls_out_k(float* __restrict__ out_attn,
                                                 float* __restrict__ out_log)
{
    const int b = blockIdx.x;
    for (int n = threadIdx.x; n < N_; n += 256) {
        float sa = 0.f, sl = 0.f;
#pragma unroll
        for (int h = 0; h < H_; h++) {
            float lg = g_cl[(size_t)(b*H_ + h)*N_ + n];
            sl += lg;
            sa += __expf(lg - g_clm[b*H_ + h]) / g_cls[b*H_ + h];
        }
        out_attn[b*N_ + n] = sa * (1.0f / H_);
        out_log [b*N_ + n] = sl * (1.0f / H_);
    }
}

// ============================================================================
extern "C" void kernel_launch(void* const* d_in, const int* in_sizes, int n_in,
                              void* d_out, int out_size)
{
    const float* x      = (const float*)d_in[0];
    const float* w_qkv  = (const float*)d_in[1];
    const float* b_qkv  = (const float*)d_in[2];
    const float* w_proj = (const float*)d_in[3];
    const float* b_proj = (const float*)d_in[4];
    float* out = (float*)d_out;

    static bool attr_set = false;
    if (!attr_set) {
        cudaFuncSetAttribute(attn_tc, cudaFuncAttributeMaxDynamicSharedMemorySize,
                             256 * AST * 4);
        attr_set = true;
    }

    // 1) QKV projection (tf32 TC) -> scatter to g_qkv
    gemm_tc<<<dim3(3072/128, (M_ + 127)/128), 256>>>(x, w_qkv, b_qkv, nullptr, 0);
    // 2) CLS row-0 logits per head
    cls_logits_k<<<dim3(H_, B_), 128>>>();
    // 3) fused attention (tf32 TC) -> g_attn
    attn_tc<<<dim3(10, H_, B_), 128, 256 * AST * 4>>>();
    // 4) CLS averages
    cls_out_k<<<B_, 256>>>(out + OFF_ATTN, out + OFF_LOG);
    // 5) output projection (tf32 TC) -> d_out
    gemm_tc<<<dim3(1024/128, (M_ + 127)/128), 256>>>(nullptr, w_proj, b_proj, out, 1);
}